// round 9
// baseline (speedup 1.0000x reference)
#include <cuda_runtime.h>
#include <cuda_bf16.h>
#include <cuda_fp16.h>

// 3D LUT trilinear interpolation.
// x:   [8, 3, 1920, 1080] f32
// lut: [3, 33, 33, 33]    f32  (indexed [chan, b, g, r], r fastest)
// out: [8, 3, 1920, 1080] f32  (same layout as x)
//
// R8: R7's crash was a non-representable magic constant (12582911.5f rounds
// to 12582912.0f -> round-to-nearest instead of floor -> i=32 OOB).
// Correct floor construction: t = fmaf(v, invbin, -0.5f) (single-rounded,
// t in [-0.5, 31.5)), f = t + 2^23*1.5 -> integer part = round(t) = floor(xv);
// integer ties round either way but both (k, 0) and (k-1, 1) lerp identically.
// Keeps: bf16x2 r-pair table (SHF/LOP3 unpack, no cvt pipe), 1 channel/CTA,
// 139KB smem, x-prefetch pipeline.

#define NPLANE   (1920 * 1080)        // 2,073,600 (divisible by 4)
#define NBATCH   8
#define NPIX     (NBATCH * NPLANE)    // 16,588,800
#define LUTC     35937                // 33^3
#define PACKN    (33 * 33 * 32)       // 34,848 packed bf16x2 entries
#define G_STRIDE 32
#define B_STRIDE (33 * 32)            // 1056
#define THREADS  1024
#define NCHUNK   148
#define SMEM_BYTES (PACKN * 4)        // 139,392 B

// floor+frac for xv = v*invbin in [0, 32), no cvt-pipe ops.
__device__ __forceinline__ void fidx(float v, float invbin, int& i, float& fr) {
    float xv = v * invbin;
    float t  = fmaf(v, invbin, -0.5f);          // in [-0.5, 31.5)
    float f  = t + 12582912.0f;                 // int part = round(t) = floor(xv)
    i  = __float_as_int(f) - 0x4B400000;        // low mantissa bits = integer
    fr = xv - (f - 12582912.0f);                // frac in [0, 1]
}

__device__ __forceinline__ float interp1(const unsigned* __restrict__ slut2,
                                         float r, float g, float b,
                                         float invbin) {
    int ir, ig, ib;
    float rd, gd, bd;
    fidx(r, invbin, ir, rd);
    fidx(g, invbin, ig, gd);
    fidx(b, invbin, ib, bd);
    int base = ib * B_STRIDE + ig * G_STRIDE + ir;

    unsigned p00 = slut2[base];                         // (v000, v001) bf16x2
    unsigned p01 = slut2[base + G_STRIDE];              // (v010, v011)
    unsigned p10 = slut2[base + B_STRIDE];              // (v100, v101)
    unsigned p11 = slut2[base + B_STRIDE + G_STRIDE];   // (v110, v111)

    // bf16 unpack via bit ops: lo -> <<16, hi -> mask. No cvt pipe.
    float a00 = __uint_as_float(p00 << 16), b00 = __uint_as_float(p00 & 0xFFFF0000u);
    float a01 = __uint_as_float(p01 << 16), b01 = __uint_as_float(p01 & 0xFFFF0000u);
    float a10 = __uint_as_float(p10 << 16), b10 = __uint_as_float(p10 & 0xFFFF0000u);
    float a11 = __uint_as_float(p11 << 16), b11 = __uint_as_float(p11 & 0xFFFF0000u);

    float c00 = fmaf(rd, b00 - a00, a00);
    float c01 = fmaf(rd, b01 - a01, a01);
    float c10 = fmaf(rd, b10 - a10, a10);
    float c11 = fmaf(rd, b11 - a11, a11);
    float c0  = fmaf(gd, c01 - c00, c00);
    float c1  = fmaf(gd, c11 - c10, c10);
    return fmaf(bd, c1 - c0, c0);
}

__global__ void __launch_bounds__(THREADS, 1)
lut3d_kernel(const float* __restrict__ lut,
             const float* __restrict__ x,
             float* __restrict__ out) {
    extern __shared__ unsigned slut2[];

    const int chan  = blockIdx.x % 3;
    const int chunk = blockIdx.x / 3;

    // Build packed bf16x2 table: slut2[(ib*33+ig)*32 + ir] = (v[r], v[r+1]).
    const float* __restrict__ lc = lut + chan * LUTC;
    for (int i = threadIdx.x; i < PACKN; i += THREADS) {
        int ir   = i & 31;
        int rest = i >> 5;             // ib*33 + ig
        int src  = rest * 33 + ir;
        unsigned lo = (unsigned)__bfloat16_as_ushort(__float2bfloat16_rn(lc[src]));
        unsigned hi = (unsigned)__bfloat16_as_ushort(__float2bfloat16_rn(lc[src + 1]));
        slut2[i] = lo | (hi << 16);
    }
    __syncthreads();

    const float invbin = 32.0f / 1.000001f;  // 1/binsize

    const int ngroups = NPIX / 4;
    const int per     = (ngroups + NCHUNK - 1) / NCHUNK;
    const int gbeg    = chunk * per;
    const int gend    = min(gbeg + per, ngroups);

    int gidx = gbeg + (int)threadIdx.x;
    if (gidx >= gend) return;

    // Prologue: load first group's pixels.
    int q    = gidx * 4;
    int bimg = q / NPLANE;
    int p    = q - bimg * NPLANE;
    const float* xb = x + (size_t)bimg * 3 * NPLANE + p;
    float4 r4 = *(const float4*)(xb);
    float4 g4 = *(const float4*)(xb + NPLANE);
    float4 b4 = *(const float4*)(xb + 2 * NPLANE);

    for (;;) {
        const int ngidx = gidx + THREADS;
        const bool has_next = ngidx < gend;

        // Prefetch next group's x while current group's gathers/lerps run.
        int nbimg = 0, np = 0;
        float4 nr4, ng4, nb4;
        if (has_next) {
            int nq = ngidx * 4;
            nbimg  = nq / NPLANE;
            np     = nq - nbimg * NPLANE;
            const float* nxb = x + (size_t)nbimg * 3 * NPLANE + np;
            nr4 = *(const float4*)(nxb);
            ng4 = *(const float4*)(nxb + NPLANE);
            nb4 = *(const float4*)(nxb + 2 * NPLANE);
        }

        float4 o;
        o.x = interp1(slut2, r4.x, g4.x, b4.x, invbin);
        o.y = interp1(slut2, r4.y, g4.y, b4.y, invbin);
        o.z = interp1(slut2, r4.z, g4.z, b4.z, invbin);
        o.w = interp1(slut2, r4.w, g4.w, b4.w, invbin);
        *(float4*)(out + (size_t)bimg * 3 * NPLANE + (size_t)chan * NPLANE + p) = o;

        if (!has_next) break;
        gidx = ngidx; bimg = nbimg; p = np;
        r4 = nr4; g4 = ng4; b4 = nb4;
    }
}

extern "C" void kernel_launch(void* const* d_in, const int* in_sizes, int n_in,
                              void* d_out, int out_size) {
    const float* lut = (const float*)d_in[0];
    const float* x   = (const float*)d_in[1];
    float* out       = (float*)d_out;

    cudaFuncSetAttribute(lut3d_kernel,
                         cudaFuncAttributeMaxDynamicSharedMemorySize,
                         SMEM_BYTES);
    lut3d_kernel<<<3 * NCHUNK, THREADS, SMEM_BYTES>>>(lut, x, out);
}

// round 10
// speedup vs baseline: 1.0623x; 1.0623x over previous
#include <cuda_runtime.h>
#include <cuda_bf16.h>
#include <cuda_fp16.h>

// 3D LUT trilinear interpolation.
// x:   [8, 3, 1920, 1080] f32
// lut: [3, 33, 33, 33]    f32  (indexed [chan, b, g, r], r fastest)
// out: [8, 3, 1920, 1080] f32  (same layout as x)
//
// R9: persistent single-wave grid (148 CTAs = 1/SM), each CTA pinned to ONE
// channel (bid % 3) -> the 139KB smem table is built once per SM instead of
// 3x (444-CTA/3-wave version repaid the ~5-8us prologue every wave).
// Table reverted to fp16 r-pairs (rel_err 1.1e-4 with 9x margin; bf16 was
// 8.8e-4 - too close to the 1e-3 threshold). Keeps exact magic-number floor
// and the x-prefetch software pipeline (regs 56 < 64 cap, no spills).

#define NPLANE   (1920 * 1080)        // 2,073,600 (divisible by 4)
#define NBATCH   8
#define NPIX     (NBATCH * NPLANE)    // 16,588,800
#define LUTC     35937                // 33^3
#define PACKN    (33 * 33 * 32)       // 34,848 packed half2 entries
#define G_STRIDE 32
#define B_STRIDE (33 * 32)            // 1056
#define THREADS  1024
#define NCTA     148
#define SMEM_BYTES (PACKN * 4)        // 139,392 B

// floor+frac for xv = v*invbin in [0, 32), no cvt-pipe ops, exact floor.
// t = fmaf(v, invbin, -0.5f) in [-0.5, 31.5); f = t + 2^23*1.5 has integer
// part round(t) = floor(xv) (integer-xv ties round either way; (k,0) and
// (k-1,1) lerp identically).
__device__ __forceinline__ void fidx(float v, float invbin, int& i, float& fr) {
    float xv = v * invbin;
    float t  = fmaf(v, invbin, -0.5f);
    float f  = t + 12582912.0f;
    i  = __float_as_int(f) - 0x4B400000;
    fr = xv - (f - 12582912.0f);
}

__device__ __forceinline__ float interp1(const unsigned* __restrict__ slut2,
                                         float r, float g, float b,
                                         float invbin) {
    int ir, ig, ib;
    float rd, gd, bd;
    fidx(r, invbin, ir, rd);
    fidx(g, invbin, ig, gd);
    fidx(b, invbin, ib, bd);
    int base = ib * B_STRIDE + ig * G_STRIDE + ir;

    unsigned p00 = slut2[base];                         // (v000, v001) fp16x2
    unsigned p01 = slut2[base + G_STRIDE];              // (v010, v011)
    unsigned p10 = slut2[base + B_STRIDE];              // (v100, v101)
    unsigned p11 = slut2[base + B_STRIDE + G_STRIDE];   // (v110, v111)

    float2 f00 = __half22float2(*(const __half2*)&p00);
    float2 f01 = __half22float2(*(const __half2*)&p01);
    float2 f10 = __half22float2(*(const __half2*)&p10);
    float2 f11 = __half22float2(*(const __half2*)&p11);

    float c00 = fmaf(rd, f00.y - f00.x, f00.x);
    float c01 = fmaf(rd, f01.y - f01.x, f01.x);
    float c10 = fmaf(rd, f10.y - f10.x, f10.x);
    float c11 = fmaf(rd, f11.y - f11.x, f11.x);
    float c0  = fmaf(gd, c01 - c00, c00);
    float c1  = fmaf(gd, c11 - c10, c10);
    return fmaf(bd, c1 - c0, c0);
}

__global__ void __launch_bounds__(THREADS, 1)
lut3d_kernel(const float* __restrict__ lut,
             const float* __restrict__ x,
             float* __restrict__ out) {
    extern __shared__ unsigned slut2[];

    // Persistent CTA, fixed channel: chan0 -> 50 CTAs, chan1/2 -> 49 CTAs.
    const int chan = blockIdx.x % 3;
    const int cid  = blockIdx.x / 3;                    // id within channel
    const int ncta = (chan == 0) ? ((NCTA + 2) / 3) : ((NCTA - chan) / 3 + ((NCTA - chan) % 3 ? 1 : 0));
    // simpler exact count: number of bids in [0,NCTA) with bid%3==chan
    const int nchan = (NCTA - chan + 2) / 3;

    // Build packed half2 table once: slut2[(ib*33+ig)*32+ir] = (v[r],v[r+1]).
    const float* __restrict__ lc = lut + chan * LUTC;
    for (int i = threadIdx.x; i < PACKN; i += THREADS) {
        int ir   = i & 31;
        int rest = i >> 5;             // ib*33 + ig
        int src  = rest * 33 + ir;
        __half2 h = __floats2half2_rn(lc[src], lc[src + 1]);
        slut2[i] = *(const unsigned*)&h;
    }
    __syncthreads();

    const float invbin = 32.0f / 1.000001f;  // 1/binsize

    const int ngroups = NPIX / 4;
    const int per     = (ngroups + nchan - 1) / nchan;
    const int gbeg    = cid * per;
    const int gend    = min(gbeg + per, ngroups);

    int gidx = gbeg + (int)threadIdx.x;
    if (gidx >= gend) return;

    // Prologue: load first group's pixels.
    int q    = gidx * 4;
    int bimg = q / NPLANE;
    int p    = q - bimg * NPLANE;
    const float* xb = x + (size_t)bimg * 3 * NPLANE + p;
    float4 r4 = *(const float4*)(xb);
    float4 g4 = *(const float4*)(xb + NPLANE);
    float4 b4 = *(const float4*)(xb + 2 * NPLANE);

    for (;;) {
        const int ngidx = gidx + THREADS;
        const bool has_next = ngidx < gend;

        // Prefetch next group's x while current group's gathers/lerps run.
        int nbimg = 0, np = 0;
        float4 nr4, ng4, nb4;
        if (has_next) {
            int nq = ngidx * 4;
            nbimg  = nq / NPLANE;
            np     = nq - nbimg * NPLANE;
            const float* nxb = x + (size_t)nbimg * 3 * NPLANE + np;
            nr4 = *(const float4*)(nxb);
            ng4 = *(const float4*)(nxb + NPLANE);
            nb4 = *(const float4*)(nxb + 2 * NPLANE);
        }

        float4 o;
        o.x = interp1(slut2, r4.x, g4.x, b4.x, invbin);
        o.y = interp1(slut2, r4.y, g4.y, b4.y, invbin);
        o.z = interp1(slut2, r4.z, g4.z, b4.z, invbin);
        o.w = interp1(slut2, r4.w, g4.w, b4.w, invbin);
        *(float4*)(out + (size_t)bimg * 3 * NPLANE + (size_t)chan * NPLANE + p) = o;

        if (!has_next) break;
        gidx = ngidx; bimg = nbimg; p = np;
        r4 = nr4; g4 = ng4; b4 = nb4;
    }
}

extern "C" void kernel_launch(void* const* d_in, const int* in_sizes, int n_in,
                              void* d_out, int out_size) {
    const float* lut = (const float*)d_in[0];
    const float* x   = (const float*)d_in[1];
    float* out       = (float*)d_out;

    cudaFuncSetAttribute(lut3d_kernel,
                         cudaFuncAttributeMaxDynamicSharedMemorySize,
                         SMEM_BYTES);
    lut3d_kernel<<<NCTA, THREADS, SMEM_BYTES>>>(lut, x, out);
}

// round 11
// speedup vs baseline: 1.0626x; 1.0003x over previous
#include <cuda_runtime.h>
#include <cuda_bf16.h>
#include <cuda_fp16.h>

// 3D LUT trilinear interpolation.
// x:   [8, 3, 1920, 1080] f32
// lut: [3, 33, 33, 33]    f32  (indexed [chan, b, g, r], r fastest)
// out: [8, 3, 1920, 1080] f32  (same layout as x)
//
// R10: explicit gather batching. Inner loop phases: (1) all 4 pixels'
// indices/fracs, (2) all 16 LDS issued back-to-back into an array (max
// shared-pipe MLP: latency + conflict replays overlap), (3) next-group x
// prefetch LDGs, (4) unpack + lerp + store. Register budget ~58 < 64 cap.
// Keeps: persistent single-wave 148-CTA grid pinned 1 channel/CTA, fp16
// r-pair table (139KB smem), exact magic-number floor.

#define NPLANE   (1920 * 1080)        // 2,073,600 (divisible by 4)
#define NBATCH   8
#define NPIX     (NBATCH * NPLANE)    // 16,588,800
#define LUTC     35937                // 33^3
#define PACKN    (33 * 33 * 32)       // 34,848 packed half2 entries
#define G_STRIDE 32
#define B_STRIDE (33 * 32)            // 1056
#define THREADS  1024
#define NCTA     148
#define SMEM_BYTES (PACKN * 4)        // 139,392 B

// floor+frac for xv = v*invbin in [0, 32): exact, no cvt-pipe ops.
__device__ __forceinline__ void fidx(float v, float invbin, int& i, float& fr) {
    float xv = v * invbin;
    float t  = fmaf(v, invbin, -0.5f);          // in [-0.5, 31.5)
    float f  = t + 12582912.0f;                 // int part = floor(xv)
    i  = __float_as_int(f) - 0x4B400000;
    fr = xv - (f - 12582912.0f);
}

__global__ void __launch_bounds__(THREADS, 1)
lut3d_kernel(const float* __restrict__ lut,
             const float* __restrict__ x,
             float* __restrict__ out) {
    extern __shared__ unsigned slut2[];

    const int chan  = blockIdx.x % 3;
    const int cid   = blockIdx.x / 3;
    const int nchan = (NCTA - chan + 2) / 3;    // CTAs serving this channel

    // Build packed half2 table: slut2[(ib*33+ig)*32 + ir] = (v[r], v[r+1]).
    const float* __restrict__ lc = lut + chan * LUTC;
    for (int i = threadIdx.x; i < PACKN; i += THREADS) {
        int ir   = i & 31;
        int rest = i >> 5;
        int src  = rest * 33 + ir;
        __half2 h = __floats2half2_rn(lc[src], lc[src + 1]);
        slut2[i] = *(const unsigned*)&h;
    }
    __syncthreads();

    const float invbin = 32.0f / 1.000001f;

    const int ngroups = NPIX / 4;
    const int per     = (ngroups + nchan - 1) / nchan;
    const int gbeg    = cid * per;
    const int gend    = min(gbeg + per, ngroups);

    int gidx = gbeg + (int)threadIdx.x;
    if (gidx >= gend) return;

    // Prologue: first group's x.
    int q    = gidx * 4;
    int bimg = q / NPLANE;
    int p    = q - bimg * NPLANE;
    const float* xb = x + (size_t)bimg * 3 * NPLANE + p;
    float4 r4 = *(const float4*)(xb);
    float4 g4 = *(const float4*)(xb + NPLANE);
    float4 b4 = *(const float4*)(xb + 2 * NPLANE);

    for (;;) {
        // Phase 1: indices + fracs for all 4 pixels.
        float rv[4] = {r4.x, r4.y, r4.z, r4.w};
        float gv[4] = {g4.x, g4.y, g4.z, g4.w};
        float bv[4] = {b4.x, b4.y, b4.z, b4.w};
        int   base[4];
        float rd[4], gd[4], bd[4];
        #pragma unroll
        for (int k = 0; k < 4; k++) {
            int ir, ig, ib;
            fidx(rv[k], invbin, ir, rd[k]);
            fidx(gv[k], invbin, ig, gd[k]);
            fidx(bv[k], invbin, ib, bd[k]);
            base[k] = ib * B_STRIDE + ig * G_STRIDE + ir;
        }

        // Phase 2: all 16 gathers issued back-to-back.
        unsigned w[16];
        #pragma unroll
        for (int k = 0; k < 4; k++) {
            w[4*k + 0] = slut2[base[k]];
            w[4*k + 1] = slut2[base[k] + G_STRIDE];
            w[4*k + 2] = slut2[base[k] + B_STRIDE];
            w[4*k + 3] = slut2[base[k] + B_STRIDE + G_STRIDE];
        }

        // Phase 3: prefetch next group's x (LDG latency hides under lerps).
        const int ngidx = gidx + THREADS;
        const bool has_next = ngidx < gend;
        int nbimg = 0, np = 0;
        float4 nr4, ng4, nb4;
        if (has_next) {
            int nq = ngidx * 4;
            nbimg  = nq / NPLANE;
            np     = nq - nbimg * NPLANE;
            const float* nxb = x + (size_t)nbimg * 3 * NPLANE + np;
            nr4 = *(const float4*)(nxb);
            ng4 = *(const float4*)(nxb + NPLANE);
            nb4 = *(const float4*)(nxb + 2 * NPLANE);
        }

        // Phase 4: unpack + lerp + store.
        float o[4];
        #pragma unroll
        for (int k = 0; k < 4; k++) {
            float2 f00 = __half22float2(*(const __half2*)&w[4*k + 0]);
            float2 f01 = __half22float2(*(const __half2*)&w[4*k + 1]);
            float2 f10 = __half22float2(*(const __half2*)&w[4*k + 2]);
            float2 f11 = __half22float2(*(const __half2*)&w[4*k + 3]);
            float c00 = fmaf(rd[k], f00.y - f00.x, f00.x);
            float c01 = fmaf(rd[k], f01.y - f01.x, f01.x);
            float c10 = fmaf(rd[k], f10.y - f10.x, f10.x);
            float c11 = fmaf(rd[k], f11.y - f11.x, f11.x);
            float c0  = fmaf(gd[k], c01 - c00, c00);
            float c1  = fmaf(gd[k], c11 - c10, c10);
            o[k] = fmaf(bd[k], c1 - c0, c0);
        }
        *(float4*)(out + (size_t)bimg * 3 * NPLANE + (size_t)chan * NPLANE + p)
            = make_float4(o[0], o[1], o[2], o[3]);

        if (!has_next) break;
        gidx = ngidx; bimg = nbimg; p = np;
        r4 = nr4; g4 = ng4; b4 = nb4;
    }
}

extern "C" void kernel_launch(void* const* d_in, const int* in_sizes, int n_in,
                              void* d_out, int out_size) {
    const float* lut = (const float*)d_in[0];
    const float* x   = (const float*)d_in[1];
    float* out       = (float*)d_out;

    cudaFuncSetAttribute(lut3d_kernel,
                         cudaFuncAttributeMaxDynamicSharedMemorySize,
                         SMEM_BYTES);
    lut3d_kernel<<<NCTA, THREADS, SMEM_BYTES>>>(lut, x, out);
}